// round 3
// baseline (speedup 1.0000x reference)
#include <cuda_runtime.h>

#define DD   256
#define NN   8192
#define EE   8191
#define ALPHA 0.2f

// ---------------- scratch (allocation-free __device__ globals, zero-init) -------
// per-output-row gather tables: out_row r = lrelu((cA*x[sA] + cB*x[sB]) @ W^T)
// rows never written by k_pre keep static 0 (correct default), every written row
// gets the same value on every call -> deterministic across graph replays.
__device__ float g_cA[NN];
__device__ float g_cB[NN];
__device__ int   g_sA[NN];
__device__ int   g_sB[NN];

// ---------------- K1: fused w-vectors + per-edge logits + scatter ----------------
// 32 blocks x 256 threads. Each block redundantly computes w1 = a[0:D]^T W and
// w2 = a[D:2D]^T W into smem, then 8 warps handle 32 edges each (warp per edge).
__global__ __launch_bounds__(256) void k_pre(
    const float* __restrict__ x, const float* __restrict__ W,
    const float* __restrict__ a,
    const int* __restrict__ dep, const int* __restrict__ gov)
{
    __shared__ float w1s[DD];
    __shared__ float w2s[DD];
    int tid = threadIdx.x;

    // phase 1: w1[t], w2[t]
    {
        float a1 = 0.f, a2 = 0.f;
#pragma unroll 8
        for (int j = 0; j < DD; j++) {
            float wv = W[j * DD + tid];
            a1 += a[j] * wv;
            a2 += a[DD + j] * wv;
        }
        w1s[tid] = a1; w2s[tid] = a2;
    }
    __syncthreads();

    // phase 2: one warp per edge, 32 edges per warp
    int w    = tid >> 5;
    int lane = tid & 31;
    int e0   = blockIdx.x * 256 + w * 32;

    int gv = (e0 + lane < EE) ? gov[e0 + lane] : 0;
    int dv = (e0 + lane < EE) ? dep[e0 + lane] : 0;

    const float4* x4  = (const float4*)x;
    const float4* w14 = (const float4*)w1s;
    const float4* w24 = (const float4*)w2s;
    float4 wa = w14[lane * 2], wb = w14[lane * 2 + 1];
    float4 va = w24[lane * 2], vb = w24[lane * 2 + 1];

#pragma unroll 4
    for (int i = 0; i < 32; i++) {
        if (e0 + i >= EE) break;
        int g = __shfl_sync(0xFFFFFFFFu, gv, i);
        int d = __shfl_sync(0xFFFFFFFFu, dv, i);
        float4 xa = x4[g * 64 + lane * 2], xb = x4[g * 64 + lane * 2 + 1];
        float4 ya = x4[d * 64 + lane * 2], yb = x4[d * 64 + lane * 2 + 1];
        float s = xa.x * wa.x + xa.y * wa.y + xa.z * wa.z + xa.w * wa.w
                + xb.x * wb.x + xb.y * wb.y + xb.z * wb.z + xb.w * wb.w
                + ya.x * va.x + ya.y * va.y + ya.z * va.z + ya.w * va.w
                + yb.x * vb.x + yb.y * vb.y + yb.z * vb.z + yb.w * vb.w;
#pragma unroll
        for (int o = 16; o; o >>= 1)
            s += __shfl_xor_sync(0xFFFFFFFFu, s, o);
        if (lane == 0) {
            float coef = (s > 0.f) ? 1.f : (1.f / (float)NN);
            g_cA[d] = 1.f;  g_sA[d] = g;   // h[dep]  = Hx[gov]
            g_cB[g] = coef; g_sB[g] = d;   // h[gov] += coef * Hx[dep]
        }
    }
}

// ---------------- K2: fused gather + tf32 tensor-core GEMM + leaky relu ---------
__device__ __forceinline__ unsigned f2tf(float f) {
    unsigned r; asm("cvt.rna.tf32.f32 %0, %1;" : "=r"(r) : "f"(f)); return r;
}
__device__ __forceinline__ float tfbits(float f) { return __uint_as_float(f2tf(f)); }
__device__ __forceinline__ float lrelu(float v) { return v > 0.f ? v : ALPHA * v; }
__device__ __forceinline__ unsigned su32(const void* p) {
    return (unsigned)__cvta_generic_to_shared(p);
}

// BM=128, BN=128, BK=32; 16 warps in 4(m) x 4(n); warp tile 32x32 (m16n8k8)
__global__ __launch_bounds__(512, 1) void k_gemm(
    const float* __restrict__ x, const float* __restrict__ W,
    float* __restrict__ out)
{
    __shared__ float As[128 * 36];   // [row][36] padded: ldmatrix conflict-free
    __shared__ float Bs[128 * 36];

    int tid = threadIdx.x;
    int m0 = blockIdx.y * 128;
    int n0 = blockIdx.x * 128;

    // ---- global-load assignment: 4 threads per row, 2 float4 each (BK=32) ----
    int arow = tid >> 2;          // 0..127
    int h    = tid & 3;           // quarter of the 32-float k-slab
    int row  = m0 + arow;
    float cA = g_cA[row], cB = g_cB[row];
    int   sA = g_sA[row], sB = g_sB[row];

    const float4* x4 = (const float4*)x;
    const float4* W4 = (const float4*)W;
    int aOff = sA * 64 + h * 2;
    int bOff = sB * 64 + h * 2;
    int wOff = (n0 + arow) * 64 + h * 2;
    int st0  = arow * 36 + h * 8;    // smem store base (floats)

    float4 rg[2], rb[2], rw[2];
#pragma unroll
    for (int j = 0; j < 2; j++) { rg[j] = x4[aOff + j]; rb[j] = x4[bOff + j]; rw[j] = W4[wOff + j]; }

    // ---- fragment addressing: warp (wm 4) x (wn 4), tile 32x32 ----
    int wid  = tid >> 5, lane = tid & 31;
    int wm   = (wid & 3) * 32;
    int wn   = (wid >> 2) * 32;
    int aRow = wm + (lane & 7) + ((lane & 8) ? 8 : 0);
    int aCol = (lane & 16) ? 4 : 0;
    unsigned aBase = su32(&As[aRow * 36 + aCol]);
    int bRow = wn + (lane & 7);
    int bCol = (lane & 8) ? 4 : 0;
    unsigned bBase = su32(&Bs[bRow * 36 + bCol]);

    float acc[2][4][4];
#pragma unroll
    for (int i = 0; i < 2; i++)
#pragma unroll
        for (int j = 0; j < 4; j++)
#pragma unroll
            for (int v = 0; v < 4; v++) acc[i][j][v] = 0.f;

#pragma unroll 1
    for (int kt = 0; kt < 8; kt++) {
        // stage tile (combine A gather, round both operands to tf32 once)
#pragma unroll
        for (int j = 0; j < 2; j++) {
            int o = st0 + j * 4;
            As[o + 0] = tfbits(cA * rg[j].x + cB * rb[j].x);
            As[o + 1] = tfbits(cA * rg[j].y + cB * rb[j].y);
            As[o + 2] = tfbits(cA * rg[j].z + cB * rb[j].z);
            As[o + 3] = tfbits(cA * rg[j].w + cB * rb[j].w);
            Bs[o + 0] = tfbits(rw[j].x);
            Bs[o + 1] = tfbits(rw[j].y);
            Bs[o + 2] = tfbits(rw[j].z);
            Bs[o + 3] = tfbits(rw[j].w);
        }
        __syncthreads();
        if (kt < 7) {                    // prefetch next k-slab into registers
            int kq = (kt + 1) * 8;
#pragma unroll
            for (int j = 0; j < 2; j++) {
                rg[j] = x4[aOff + kq + j];
                rb[j] = x4[bOff + kq + j];
                rw[j] = W4[wOff + kq + j];
            }
        }
#pragma unroll
        for (int ks = 0; ks < 4; ks++) {
            int k = ks * 8;
            unsigned af[2][4], bf[4][2];
#pragma unroll
            for (int mf = 0; mf < 2; mf++)
                asm volatile("ldmatrix.sync.aligned.m8n8.x4.shared.b16 {%0,%1,%2,%3}, [%4];"
                    : "=r"(af[mf][0]), "=r"(af[mf][1]), "=r"(af[mf][2]), "=r"(af[mf][3])
                    : "r"(aBase + (unsigned)((mf * 576 + k) * 4)));
#pragma unroll
            for (int nf = 0; nf < 4; nf++)
                asm volatile("ldmatrix.sync.aligned.m8n8.x2.shared.b16 {%0,%1}, [%2];"
                    : "=r"(bf[nf][0]), "=r"(bf[nf][1])
                    : "r"(bBase + (unsigned)((nf * 288 + k) * 4)));
#pragma unroll
            for (int mf = 0; mf < 2; mf++)
#pragma unroll
                for (int nf = 0; nf < 4; nf++)
                    asm volatile(
                        "mma.sync.aligned.m16n8k8.row.col.f32.tf32.tf32.f32 "
                        "{%0,%1,%2,%3}, {%4,%5,%6,%7}, {%8,%9}, {%0,%1,%2,%3};"
                        : "+f"(acc[mf][nf][0]), "+f"(acc[mf][nf][1]),
                          "+f"(acc[mf][nf][2]), "+f"(acc[mf][nf][3])
                        : "r"(af[mf][0]), "r"(af[mf][1]), "r"(af[mf][2]), "r"(af[mf][3]),
                          "r"(bf[nf][0]), "r"(bf[nf][1]));
        }
        __syncthreads();
    }

    // ---- epilogue: leaky relu, float2 stores ----
    int er = m0 + wm + (lane >> 2);
    int ec = n0 + wn + (lane & 3) * 2;
#pragma unroll
    for (int mf = 0; mf < 2; mf++) {
#pragma unroll
        for (int nf = 0; nf < 4; nf++) {
            float2 v0, v1;
            v0.x = lrelu(acc[mf][nf][0]); v0.y = lrelu(acc[mf][nf][1]);
            v1.x = lrelu(acc[mf][nf][2]); v1.y = lrelu(acc[mf][nf][3]);
            *(float2*)&out[(er + mf * 16) * DD + ec + nf * 8]     = v0;
            *(float2*)&out[(er + mf * 16 + 8) * DD + ec + nf * 8] = v1;
        }
    }
}

// ---------------- launch ---------------------------------------------------------
extern "C" void kernel_launch(void* const* d_in, const int* in_sizes, int n_in,
                              void* d_out, int out_size) {
    const float* x   = (const float*)d_in[0];
    const float* W   = (const float*)d_in[1];
    const float* a   = (const float*)d_in[2];
    const int*   dep = (const int*)d_in[3];
    const int*   gov = (const int*)d_in[4];
    float* out = (float*)d_out;

    k_pre<<<32, 256>>>(x, W, a, dep, gov);
    k_gemm<<<dim3(2, 64), 512>>>(x, W, out);
}